// round 1
// baseline (speedup 1.0000x reference)
#include <cuda_runtime.h>

// MutualProjection: B=8, V=4, J=21, IMG=128
// out = [depth_imgs (B,V,V,128,128) f32][proj (B,V,V,J,3,1) f32]

#define IMG     128
#define BIGV    1000000.0f
#define B_      8
#define V_      4
#define J_      21
#define SPLIT   8                 // row-bands per image
#define ROWS_PER (IMG / SPLIT)    // 16
#define PIX_PER_THREAD ((ROWS_PER * IMG) / 256)  // 8

__global__ __launch_bounds__(256)
void mutual_projection_kernel(
    const float* __restrict__ cam,     // (B,V,4,4)
    const float* __restrict__ inv,     // (B,V,4,4)
    const float* __restrict__ joints,  // (B,V,J,3)
    const float* __restrict__ rads,    // (J)
    float* __restrict__ depth_out,     // (B,V,V,128,128)
    float* __restrict__ proj_out)      // (B,V,V,J,3)
{
    __shared__ float M[12];                      // rows 0..2 of mutual (3x4)
    __shared__ float px[J_], py[J_], pz[J_], r2s[J_];

    const int blk = blockIdx.x >> 3;   // image index in [0,128)
    const int s   = blockIdx.x & 7;    // row-band
    const int b   = blk >> 4;          // /(V*V)
    const int i   = (blk >> 2) & 3;
    const int j   = blk & 3;
    const int t   = threadIdx.x;

    const float* camM = cam + ((b * V_ + i) << 4);
    const float* invM = inv + ((b * V_ + j) << 4);

    // mutual[b,i,j,x,z] = sum_y inv[b,j,x,y] * cam[b,i,y,z]; need x,z in [0,3)x[0,4)
    if (t < 12) {
        const int x = t >> 2, z = t & 3;
        float acc =        invM[x * 4 + 0] * camM[0 * 4 + z];
        acc = fmaf(invM[x * 4 + 1], camM[1 * 4 + z], acc);
        acc = fmaf(invM[x * 4 + 2], camM[2 * 4 + z], acc);
        acc = fmaf(invM[x * 4 + 3], camM[3 * 4 + z], acc);
        M[t] = acc;
    }
    __syncthreads();

    // proj[b,i,j,k,:] = R @ joints[b,i,k] + t_vec ; also publish ball params
    if (t < J_) {
        const float* jp = joints + ((b * V_ + i) * J_ + t) * 3;
        const float jx = jp[0], jy = jp[1], jz = jp[2];
        const float qx = fmaf(M[2],  jz, fmaf(M[1], jy, M[0] * jx)) + M[3];
        const float qy = fmaf(M[6],  jz, fmaf(M[5], jy, M[4] * jx)) + M[7];
        const float qz = fmaf(M[10], jz, fmaf(M[9], jy, M[8] * jx)) + M[11];
        px[t] = qx; py[t] = qy; pz[t] = qz;
        const float r = rads[t];
        r2s[t] = r * r;
        if (s == 0) {
            float* po = proj_out + (blk * J_ + t) * 3;
            po[0] = qx; po[1] = qy; po[2] = qz;
        }
    }
    __syncthreads();

    // Rasterize: thread t owns column (t&127), rows y0, y0+2, ... (8 of them)
    const int   x  = t & 127;
    const int   y0 = s * ROWS_PER + (t >> 7);
    const float xf = (float)x;

    float best[PIX_PER_THREAD];
#pragma unroll
    for (int q = 0; q < PIX_PER_THREAD; q++) best[q] = BIGV;

    for (int k = 0; k < J_; k++) {
        const float pxk = px[k], pyk = py[k], pzk = pz[k], r2 = r2s[k];
        const float dx  = __fsub_rn(xf, pxk);
        const float dx2 = __fmul_rn(dx, dx);
#pragma unroll
        for (int q = 0; q < PIX_PER_THREAD; q++) {
            const float yf = (float)(y0 + 2 * q);
            const float dy = __fsub_rn(yf, pyk);
            const float d2 = __fadd_rn(dx2, __fmul_rn(dy, dy));
            if (d2 < r2) {
                const float v = pzk - __fsqrt_rn(r2 - d2);
                best[q] = fminf(best[q], v);
            }
        }
    }

    float* dout = depth_out + blk * (IMG * IMG);
#pragma unroll
    for (int q = 0; q < PIX_PER_THREAD; q++) {
        dout[(y0 + 2 * q) * IMG + x] = best[q];
    }
}

extern "C" void kernel_launch(void* const* d_in, const int* in_sizes, int n_in,
                              void* d_out, int out_size)
{
    const float* cam    = (const float*)d_in[0];
    const float* inv    = (const float*)d_in[1];
    const float* joints = (const float*)d_in[2];
    const float* rads   = (const float*)d_in[3];

    float* depth = (float*)d_out;                                  // 8*4*4*128*128
    float* proj  = depth + (size_t)B_ * V_ * V_ * IMG * IMG;       // + 8*4*4*21*3

    const int grid = B_ * V_ * V_ * SPLIT;   // 1024
    mutual_projection_kernel<<<grid, 256>>>(cam, inv, joints, rads, depth, proj);
}

// round 2
// speedup vs baseline: 1.6400x; 1.6400x over previous
#include <cuda_runtime.h>

// MutualProjection: B=8, V=4, J=21, IMG=128
// out = [depth_imgs (B,V,V,128,128) f32][proj (B,V,V,J,3,1) f32]

#define IMG     128
#define BIGV    1000000.0f
#define B_      8
#define V_      4
#define J_      21
#define SPLIT   8                 // row-bands per image (16 rows each)
#define RPT     8                 // consecutive rows per thread

__global__ __launch_bounds__(256)
void mutual_projection_kernel(
    const float* __restrict__ cam,     // (B,V,4,4)
    const float* __restrict__ inv,     // (B,V,4,4)
    const float* __restrict__ joints,  // (B,V,J,3)
    const float* __restrict__ rads,    // (J)
    float* __restrict__ depth_out,     // (B,V,V,128,128)
    float* __restrict__ proj_out)      // (B,V,V,J,3)
{
    __shared__ float M[12];
    __shared__ float px[J_], py[J_], pz[J_], r2s[J_], rs[J_];

    const int blk = blockIdx.x >> 3;   // image index in [0,128)
    const int s   = blockIdx.x & 7;    // 16-row band
    const int b   = blk >> 4;
    const int i   = (blk >> 2) & 3;
    const int j   = blk & 3;
    const int t   = threadIdx.x;

    const float* camM = cam + ((b * V_ + i) << 4);
    const float* invM = inv + ((b * V_ + j) << 4);

    // mutual rows 0..2: inv[b,j] @ cam[b,i]
    if (t < 12) {
        const int x = t >> 2, z = t & 3;
        float acc =        invM[x * 4 + 0] * camM[0 * 4 + z];
        acc = fmaf(invM[x * 4 + 1], camM[1 * 4 + z], acc);
        acc = fmaf(invM[x * 4 + 2], camM[2 * 4 + z], acc);
        acc = fmaf(invM[x * 4 + 3], camM[3 * 4 + z], acc);
        M[t] = acc;
    }
    __syncthreads();

    if (t < J_) {
        const float* jp = joints + ((b * V_ + i) * J_ + t) * 3;
        const float jx = jp[0], jy = jp[1], jz = jp[2];
        const float qx = fmaf(M[2],  jz, fmaf(M[1], jy, M[0] * jx)) + M[3];
        const float qy = fmaf(M[6],  jz, fmaf(M[5], jy, M[4] * jx)) + M[7];
        const float qz = fmaf(M[10], jz, fmaf(M[9], jy, M[8] * jx)) + M[11];
        px[t] = qx; py[t] = qy; pz[t] = qz;
        const float r = rads[t];
        rs[t]  = r;
        r2s[t] = r * r;
        if (s == 0) {
            float* po = proj_out + (blk * J_ + t) * 3;
            po[0] = qx; po[1] = qy; po[2] = qz;
        }
    }
    __syncthreads();

    // Tiling: warp w owns a 32-col x 8-row tile.
    //   col  = (w&3)*32 + lane
    //   rows = y0 .. y0+7, y0 = s*16 + (w>>2)*8   (uniform across the warp)
    const int w    = t >> 5;
    const int lane = t & 31;
    const int x    = ((w & 3) << 5) | lane;
    const int y0   = (s << 4) + ((w >> 2) << 3);

    const float xf  = (float)x;
    const float y0f = (float)y0;
    const float yc  = y0f + 3.5f;       // row-group center

    float best[RPT];
#pragma unroll
    for (int q = 0; q < RPT; q++) best[q] = BIGV;

    for (int k = 0; k < J_; k++) {
        const float pyk = py[k];
        const float r   = rs[k];
        // warp-uniform row cull (+0.01 safety so rounding never culls a true hit)
        if (fabsf(pyk - yc) >= r + 3.51f) continue;

        const float pxk = px[k];
        const float r2  = r2s[k];
        const float dx  = __fsub_rn(xf, pxk);
        const float dx2 = __fmul_rn(dx, dx);
        // per-lane column cull; exact-safe: d2 = rn(dx2 + dy^2) >= dx2 >= r2
        if (dx2 >= r2) continue;

        const float pzk = pz[k];
#pragma unroll
        for (int q = 0; q < RPT; q++) {
            const float yf = y0f + (float)q;          // exact (small ints)
            const float dy = __fsub_rn(yf, pyk);
            const float d2 = __fadd_rn(dx2, __fmul_rn(dy, dy));
            if (d2 < r2) {
                best[q] = fminf(best[q], pzk - __fsqrt_rn(r2 - d2));
            }
        }
    }

    float* dout = depth_out + blk * (IMG * IMG) + y0 * IMG + x;
#pragma unroll
    for (int q = 0; q < RPT; q++) {
        dout[q * IMG] = best[q];
    }
}

extern "C" void kernel_launch(void* const* d_in, const int* in_sizes, int n_in,
                              void* d_out, int out_size)
{
    const float* cam    = (const float*)d_in[0];
    const float* inv    = (const float*)d_in[1];
    const float* joints = (const float*)d_in[2];
    const float* rads   = (const float*)d_in[3];

    float* depth = (float*)d_out;                                // 8*4*4*128*128
    float* proj  = depth + (size_t)B_ * V_ * V_ * IMG * IMG;     // + 8*4*4*21*3

    const int grid = B_ * V_ * V_ * SPLIT;   // 1024
    mutual_projection_kernel<<<grid, 256>>>(cam, inv, joints, rads, depth, proj);
}

// round 3
// speedup vs baseline: 2.3429x; 1.4286x over previous
#include <cuda_runtime.h>

// MutualProjection: B=8, V=4, J=21, IMG=128
// out = [depth_imgs (B,V,V,128,128) f32][proj (B,V,V,J,3,1) f32]

#define IMG     128
#define BIGV    1000000.0f
#define B_      8
#define V_      4
#define J_      21
#define SPLIT   8                 // row-bands per image (16 rows per CTA)
#define RPT     8                 // consecutive rows per thread

__device__ __forceinline__ float fsqrt_approx(float a) {
    float r;
    asm("sqrt.approx.f32 %0, %1;" : "=f"(r) : "f"(a));
    return r;
}

__global__ __launch_bounds__(256)
void mutual_projection_kernel(
    const float* __restrict__ cam,     // (B,V,4,4)
    const float* __restrict__ inv,     // (B,V,4,4)
    const float* __restrict__ joints,  // (B,V,J,3)
    const float* __restrict__ rads,    // (J)
    float* __restrict__ depth_out,     // (B,V,V,128,128)
    float* __restrict__ proj_out)      // (B,V,V,J,3)
{
    __shared__ float  M[12];
    __shared__ float  px[J_], py[J_], pz[J_], r2s[J_], rs[J_];
    __shared__ float4 blist[2][J_];    // per-band compacted {px,py,pz,r2}
    __shared__ int    bcnt[2];

    const int blk = blockIdx.x >> 3;   // image index in [0,128)
    const int s   = blockIdx.x & 7;    // 16-row band
    const int b   = blk >> 4;
    const int i   = (blk >> 2) & 3;
    const int j   = blk & 3;
    const int t   = threadIdx.x;

    const float* camM = cam + ((b * V_ + i) << 4);
    const float* invM = inv + ((b * V_ + j) << 4);

    // mutual rows 0..2: inv[b,j] @ cam[b,i]
    if (t < 12) {
        const int x = t >> 2, z = t & 3;
        float acc =        invM[x * 4 + 0] * camM[0 * 4 + z];
        acc = fmaf(invM[x * 4 + 1], camM[1 * 4 + z], acc);
        acc = fmaf(invM[x * 4 + 2], camM[2 * 4 + z], acc);
        acc = fmaf(invM[x * 4 + 3], camM[3 * 4 + z], acc);
        M[t] = acc;
    }
    __syncthreads();

    if (t < J_) {
        const float* jp = joints + ((b * V_ + i) * J_ + t) * 3;
        const float jx = jp[0], jy = jp[1], jz = jp[2];
        const float qx = fmaf(M[2],  jz, fmaf(M[1], jy, M[0] * jx)) + M[3];
        const float qy = fmaf(M[6],  jz, fmaf(M[5], jy, M[4] * jx)) + M[7];
        const float qz = fmaf(M[10], jz, fmaf(M[9], jy, M[8] * jx)) + M[11];
        px[t] = qx; py[t] = qy; pz[t] = qz;
        const float r = rads[t];
        rs[t]  = r;
        r2s[t] = r * r;
        if (s == 0) {
            float* po = proj_out + (blk * J_ + t) * 3;
            po[0] = qx; po[1] = qy; po[2] = qz;
        }
    }
    __syncthreads();

    // Band compaction: warp 0 -> band 0 (rows s*16..+7), warp 1 -> band 1 (+8..+15).
    // Row cull carries +0.01 safety so rounding never culls a true-inside pixel.
    const int w    = t >> 5;
    const int lane = t & 31;
    if (w < 2) {
        const float yc = (float)(s * 16 + w * 8) + 3.5f;
        bool pass = false;
        if (lane < J_) {
            pass = fabsf(py[lane] - yc) < rs[lane] + 3.51f;
        }
        const unsigned mask = __ballot_sync(0xFFFFFFFFu, pass);
        if (pass) {
            const int pos = __popc(mask & ((1u << lane) - 1u));
            blist[w][pos] = make_float4(px[lane], py[lane], pz[lane], r2s[lane]);
        }
        if (lane == 0) bcnt[w] = __popc(mask);
    }
    __syncthreads();

    // Warp tile: 32 cols x 8 consecutive rows.
    const int tb  = w >> 2;                    // band within CTA
    const int x   = ((w & 3) << 5) | lane;
    const int y0  = (s << 4) + (tb << 3);
    const float xf  = (float)x;
    const float y0f = (float)y0;

    float best[RPT];
#pragma unroll
    for (int q = 0; q < RPT; q++) best[q] = BIGV;

    const int cnt = bcnt[tb];
    for (int n = 0; n < cnt; n++) {
        const float4 p  = blist[tb][n];
        const float dx  = __fsub_rn(xf, p.x);
        const float dx2 = __fmul_rn(dx, dx);
        // per-lane column cull; exact-safe since d2 = rn(dx2 + dy^2) >= dx2
        if (dx2 >= p.w) continue;

#pragma unroll
        for (int q = 0; q < RPT; q++) {
            const float yf = y0f + (float)q;              // exact small ints
            const float dy = __fsub_rn(yf, p.y);
            const float d2 = __fadd_rn(dx2, __fmul_rn(dy, dy));
            // Unconditional value; NaN (d2>r2) is masked by the predicate,
            // and fminf(x, NaN) == x regardless.
            const float v  = p.z - fsqrt_approx(p.w - d2);
            if (d2 < p.w) best[q] = fminf(best[q], v);
        }
    }

    float* dout = depth_out + blk * (IMG * IMG) + y0 * IMG + x;
#pragma unroll
    for (int q = 0; q < RPT; q++) {
        dout[q * IMG] = best[q];
    }
}

extern "C" void kernel_launch(void* const* d_in, const int* in_sizes, int n_in,
                              void* d_out, int out_size)
{
    const float* cam    = (const float*)d_in[0];
    const float* inv    = (const float*)d_in[1];
    const float* joints = (const float*)d_in[2];
    const float* rads   = (const float*)d_in[3];

    float* depth = (float*)d_out;                                // 8*4*4*128*128
    float* proj  = depth + (size_t)B_ * V_ * V_ * IMG * IMG;     // + 8*4*4*21*3

    const int grid = B_ * V_ * V_ * SPLIT;   // 1024
    mutual_projection_kernel<<<grid, 256>>>(cam, inv, joints, rads, depth, proj);
}

// round 4
// speedup vs baseline: 2.4118x; 1.0294x over previous
#include <cuda_runtime.h>

// MutualProjection: B=8, V=4, J=21, IMG=128
// out = [depth_imgs (B,V,V,128,128) f32][proj (B,V,V,J,3,1) f32]

#define IMG     128
#define BIGV    1000000.0f
#define B_      8
#define V_      4
#define J_      21
#define SPLIT   8                 // row-bands per image (16 rows per CTA)
#define RPT     8                 // consecutive rows per thread

__device__ __forceinline__ float fsqrt_approx(float a) {
    float r;
    asm("sqrt.approx.f32 %0, %1;" : "=f"(r) : "f"(a));
    return r;
}

__global__ __launch_bounds__(256)
void mutual_projection_kernel(
    const float* __restrict__ cam,     // (B,V,4,4)
    const float* __restrict__ inv,     // (B,V,4,4)
    const float* __restrict__ joints,  // (B,V,J,3)
    const float* __restrict__ rads,    // (J)
    float* __restrict__ depth_out,     // (B,V,V,128,128)
    float* __restrict__ proj_out)      // (B,V,V,J,3)
{
    __shared__ float4 blist[2][J_];    // per-band compacted {px,py,pz,r2}
    __shared__ int    bcnt[2];

    const int blk = blockIdx.x >> 3;   // image index in [0,128)
    const int s   = blockIdx.x & 7;    // 16-row band
    const int b   = blk >> 4;
    const int i   = (blk >> 2) & 3;
    const int j   = blk & 3;
    const int t   = threadIdx.x;
    const int w   = t >> 5;
    const int lane = t & 31;

    // ---- Prologue: warps 0 and 1 each build the compacted ball list for
    //      their band using only intra-warp communication. One CTA barrier.
    if (w < 2) {
        const float* camM = cam + ((b * V_ + i) << 4);
        const float* invM = inv + ((b * V_ + j) << 4);

        // lanes 0..11: M[x][z] = sum_y inv[j][x][y] * cam[i][y][z]
        float acc = 0.0f;
        if (lane < 12) {
            const int x = lane >> 2, z = lane & 3;
            acc =              invM[x * 4 + 0] * camM[0 * 4 + z];
            acc = fmaf(invM[x * 4 + 1], camM[1 * 4 + z], acc);
            acc = fmaf(invM[x * 4 + 2], camM[2 * 4 + z], acc);
            acc = fmaf(invM[x * 4 + 3], camM[3 * 4 + z], acc);
        }
        // broadcast the 12 matrix entries to all lanes
        const unsigned FULL = 0xFFFFFFFFu;
        const float m0  = __shfl_sync(FULL, acc, 0);
        const float m1  = __shfl_sync(FULL, acc, 1);
        const float m2  = __shfl_sync(FULL, acc, 2);
        const float m3  = __shfl_sync(FULL, acc, 3);
        const float m4  = __shfl_sync(FULL, acc, 4);
        const float m5  = __shfl_sync(FULL, acc, 5);
        const float m6  = __shfl_sync(FULL, acc, 6);
        const float m7  = __shfl_sync(FULL, acc, 7);
        const float m8  = __shfl_sync(FULL, acc, 8);
        const float m9  = __shfl_sync(FULL, acc, 9);
        const float m10 = __shfl_sync(FULL, acc, 10);
        const float m11 = __shfl_sync(FULL, acc, 11);

        // lanes 0..20: project joint, row-cull for this warp's band, compact.
        bool pass = false;
        float qx = 0.f, qy = 0.f, qz = 0.f, r2 = 0.f;
        if (lane < J_) {
            const float* jp = joints + ((b * V_ + i) * J_ + lane) * 3;
            const float jx = jp[0], jy = jp[1], jz = jp[2];
            qx = fmaf(m2,  jz, fmaf(m1, jy, m0 * jx)) + m3;
            qy = fmaf(m6,  jz, fmaf(m5, jy, m4 * jx)) + m7;
            qz = fmaf(m10, jz, fmaf(m9, jy, m8 * jx)) + m11;
            const float r = rads[lane];
            r2 = r * r;
            if (w == 0 && s == 0) {
                float* po = proj_out + (blk * J_ + lane) * 3;
                po[0] = qx; po[1] = qy; po[2] = qz;
            }
            // band center = y0 + 3.5; +0.01 safety so rounding never culls
            // a true-inside pixel.
            const float yc = (float)(s * 16 + w * 8) + 3.5f;
            pass = fabsf(qy - yc) < r + 3.51f;
        }
        const unsigned mask = __ballot_sync(FULL, pass);
        if (pass) {
            const int pos = __popc(mask & ((1u << lane) - 1u));
            blist[w][pos] = make_float4(qx, qy, qz, r2);
        }
        if (lane == 0) bcnt[w] = __popc(mask);
    }
    __syncthreads();

    // ---- Rasterize: warp tile = 32 cols x 8 consecutive rows.
    const int tb  = w >> 2;                    // band within CTA
    const int x   = ((w & 3) << 5) | lane;
    const int y0  = (s << 4) + (tb << 3);
    const float xf  = (float)x;
    const float y0f = (float)y0;

    float best[RPT];
#pragma unroll
    for (int q = 0; q < RPT; q++) best[q] = BIGV;

    const int cnt = bcnt[tb];
    for (int n = 0; n < cnt; n++) {
        const float4 p  = blist[tb][n];
        const float dx  = __fsub_rn(xf, p.x);
        const float dx2 = __fmul_rn(dx, dx);
        // per-lane column cull; exact-safe since d2 = rn(dx2 + dy^2) >= dx2
        if (dx2 >= p.w) continue;

#pragma unroll
        for (int q = 0; q < RPT; q++) {
            const float yf = y0f + (float)q;              // exact small ints
            const float dy = __fsub_rn(yf, p.y);
            const float d2 = __fadd_rn(dx2, __fmul_rn(dy, dy));
            const float v  = p.z - fsqrt_approx(p.w - d2);
            if (d2 < p.w) best[q] = fminf(best[q], v);
        }
    }

    float* dout = depth_out + blk * (IMG * IMG) + y0 * IMG + x;
#pragma unroll
    for (int q = 0; q < RPT; q++) {
        dout[q * IMG] = best[q];
    }
}

extern "C" void kernel_launch(void* const* d_in, const int* in_sizes, int n_in,
                              void* d_out, int out_size)
{
    const float* cam    = (const float*)d_in[0];
    const float* inv    = (const float*)d_in[1];
    const float* joints = (const float*)d_in[2];
    const float* rads   = (const float*)d_in[3];

    float* depth = (float*)d_out;                                // 8*4*4*128*128
    float* proj  = depth + (size_t)B_ * V_ * V_ * IMG * IMG;     // + 8*4*4*21*3

    const int grid = B_ * V_ * V_ * SPLIT;   // 1024
    mutual_projection_kernel<<<grid, 256>>>(cam, inv, joints, rads, depth, proj);
}

// round 5
// speedup vs baseline: 2.4207x; 1.0037x over previous
#include <cuda_runtime.h>

// MutualProjection: B=8, V=4, J=21, IMG=128
// out = [depth_imgs (B,V,V,128,128) f32][proj (B,V,V,J,3,1) f32]

#define IMG     128
#define BIGV    1000000.0f
#define B_      8
#define V_      4
#define J_      21
#define SPLIT   8                 // row-bands per image (16 rows per CTA)
#define RPT     8                 // consecutive rows per thread

__device__ __forceinline__ float fsqrt_approx(float a) {
    float r;
    asm("sqrt.approx.f32 %0, %1;" : "=f"(r) : "f"(a));
    return r;
}

// min-blocks=8: caps regs at 32 so all 1024 CTAs are resident in ONE wave
// (8 CTAs/SM x 148 SMs = 1184 >= 1024). At 40 regs only 6/SM fit -> 1.15
// waves and a 136-CTA straggler tail that idled ~half the kernel.
__global__ __launch_bounds__(256, 8)
void mutual_projection_kernel(
    const float* __restrict__ cam,     // (B,V,4,4)
    const float* __restrict__ inv,     // (B,V,4,4)
    const float* __restrict__ joints,  // (B,V,J,3)
    const float* __restrict__ rads,    // (J)
    float* __restrict__ depth_out,     // (B,V,V,128,128)
    float* __restrict__ proj_out)      // (B,V,V,J,3)
{
    __shared__ float4 blist[2][J_];    // per-band compacted {px,py,pz,r2}
    __shared__ int    bcnt[2];

    const int blk = blockIdx.x >> 3;   // image index in [0,128)
    const int s   = blockIdx.x & 7;    // 16-row band
    const int b   = blk >> 4;
    const int i   = (blk >> 2) & 3;
    const int j   = blk & 3;
    const int t   = threadIdx.x;
    const int w   = t >> 5;
    const int lane = t & 31;

    // ---- Prologue: warps 0 and 1 each build the compacted ball list for
    //      their band using only intra-warp communication. One CTA barrier.
    if (w < 2) {
        const float* camM = cam + ((b * V_ + i) << 4);
        const float* invM = inv + ((b * V_ + j) << 4);

        // lanes 0..11: M[x][z] = sum_y inv[j][x][y] * cam[i][y][z]
        float acc = 0.0f;
        if (lane < 12) {
            const int x = lane >> 2, z = lane & 3;
            acc =              invM[x * 4 + 0] * camM[0 * 4 + z];
            acc = fmaf(invM[x * 4 + 1], camM[1 * 4 + z], acc);
            acc = fmaf(invM[x * 4 + 2], camM[2 * 4 + z], acc);
            acc = fmaf(invM[x * 4 + 3], camM[3 * 4 + z], acc);
        }
        const unsigned FULL = 0xFFFFFFFFu;
        const float m0  = __shfl_sync(FULL, acc, 0);
        const float m1  = __shfl_sync(FULL, acc, 1);
        const float m2  = __shfl_sync(FULL, acc, 2);
        const float m3  = __shfl_sync(FULL, acc, 3);
        const float m4  = __shfl_sync(FULL, acc, 4);
        const float m5  = __shfl_sync(FULL, acc, 5);
        const float m6  = __shfl_sync(FULL, acc, 6);
        const float m7  = __shfl_sync(FULL, acc, 7);
        const float m8  = __shfl_sync(FULL, acc, 8);
        const float m9  = __shfl_sync(FULL, acc, 9);
        const float m10 = __shfl_sync(FULL, acc, 10);
        const float m11 = __shfl_sync(FULL, acc, 11);

        // lanes 0..20: project joint, row-cull for this warp's band, compact.
        bool pass = false;
        float qx = 0.f, qy = 0.f, qz = 0.f, r2 = 0.f;
        if (lane < J_) {
            const float* jp = joints + ((b * V_ + i) * J_ + lane) * 3;
            const float jx = jp[0], jy = jp[1], jz = jp[2];
            qx = fmaf(m2,  jz, fmaf(m1, jy, m0 * jx)) + m3;
            qy = fmaf(m6,  jz, fmaf(m5, jy, m4 * jx)) + m7;
            qz = fmaf(m10, jz, fmaf(m9, jy, m8 * jx)) + m11;
            const float r = rads[lane];
            r2 = r * r;
            if (w == 0 && s == 0) {
                float* po = proj_out + (blk * J_ + lane) * 3;
                po[0] = qx; po[1] = qy; po[2] = qz;
            }
            // band center = y0 + 3.5; +0.01 safety so rounding never culls
            // a true-inside pixel.
            const float yc = (float)(s * 16 + w * 8) + 3.5f;
            pass = fabsf(qy - yc) < r + 3.51f;
        }
        const unsigned mask = __ballot_sync(FULL, pass);
        if (pass) {
            const int pos = __popc(mask & ((1u << lane) - 1u));
            blist[w][pos] = make_float4(qx, qy, qz, r2);
        }
        if (lane == 0) bcnt[w] = __popc(mask);
    }
    __syncthreads();

    // ---- Rasterize: warp tile = 32 cols x 8 consecutive rows.
    const int tb  = w >> 2;                    // band within CTA
    const int x   = ((w & 3) << 5) | lane;
    const int y0  = (s << 4) + (tb << 3);
    const float xf  = (float)x;
    const float y0f = (float)y0;

    float best[RPT];
#pragma unroll
    for (int q = 0; q < RPT; q++) best[q] = BIGV;

    const int cnt = bcnt[tb];
    for (int n = 0; n < cnt; n++) {
        const float4 p  = blist[tb][n];
        const float dx  = __fsub_rn(xf, p.x);
        const float dx2 = __fmul_rn(dx, dx);
        // per-lane column cull; exact-safe since d2 = rn(dx2 + dy^2) >= dx2
        if (dx2 >= p.w) continue;

#pragma unroll
        for (int q = 0; q < RPT; q++) {
            const float yf = y0f + (float)q;              // exact small ints
            const float dy = __fsub_rn(yf, p.y);
            const float d2 = __fadd_rn(dx2, __fmul_rn(dy, dy));
            const float v  = p.z - fsqrt_approx(p.w - d2);
            if (d2 < p.w) best[q] = fminf(best[q], v);
        }
    }

    float* dout = depth_out + blk * (IMG * IMG) + y0 * IMG + x;
#pragma unroll
    for (int q = 0; q < RPT; q++) {
        dout[q * IMG] = best[q];
    }
}

extern "C" void kernel_launch(void* const* d_in, const int* in_sizes, int n_in,
                              void* d_out, int out_size)
{
    const float* cam    = (const float*)d_in[0];
    const float* inv    = (const float*)d_in[1];
    const float* joints = (const float*)d_in[2];
    const float* rads   = (const float*)d_in[3];

    float* depth = (float*)d_out;                                // 8*4*4*128*128
    float* proj  = depth + (size_t)B_ * V_ * V_ * IMG * IMG;     // + 8*4*4*21*3

    const int grid = B_ * V_ * V_ * SPLIT;   // 1024
    mutual_projection_kernel<<<grid, 256>>>(cam, inv, joints, rads, depth, proj);
}